// round 1
// baseline (speedup 1.0000x reference)
#include <cuda_runtime.h>
#include <math.h>

#define T_STEPS 128
#define B_ENV   128
#define HID     512
#define TBTOT   (T_STEPS * B_ENV)
#define ZD      8
#define AD      7
#define FE      128

// ----------------------------------------------------------------------------
// Scratch (device globals; no allocation allowed)
// ----------------------------------------------------------------------------
__device__ float g_conv[TBTOT * 4096];   // conv output / fc1 input  (268 MB)
__device__ float g_h1[TBTOT * HID];
__device__ float g_h2[TBTOT * HID];
__device__ float g_xg[TBTOT * 2048];     // precomputed input gates  (134 MB)
__device__ float g_feat[TBTOT * HID];
__device__ float g_lf[TBTOT * FE];
__device__ float g_hA[B_ENV * HID];
__device__ float g_hB[B_ENV * HID];
__device__ float g_c[B_ENV * HID];

// ----------------------------------------------------------------------------
// Fused 3-conv kernel: one block per image, 256 threads (co = tid>>4, h = tid&15)
// smem input buffer uses stride-17 rows -> conflict-free LDS.
// ----------------------------------------------------------------------------
template <int KS, int P>
__device__ __forceinline__ void conv_body(const float* __restrict__ s_in,
                                          const float* __restrict__ s_w,
                                          const float* __restrict__ s_b,
                                          float* acc, int co, int h) {
    float bv = s_b[co];
#pragma unroll
    for (int w = 0; w < 16; w++) acc[w] = bv;
    for (int ci = 0; ci < 16; ci++) {
        const float* wbase = s_w + (co * 16 + ci) * KS * KS;
#pragma unroll
        for (int kh = 0; kh < KS; kh++) {
            int hy = h + kh - P;
            if (hy < 0 || hy > 15) continue;
            const float* row = s_in + ci * 272 + hy * 17;
            float rin[16];
#pragma unroll
            for (int w = 0; w < 16; w++) rin[w] = row[w];
#pragma unroll
            for (int kw = 0; kw < KS; kw++) {
                float wv = wbase[kh * KS + kw];
#pragma unroll
                for (int w = 0; w < 16; w++) {
                    int xi = w + kw - P;
                    if (xi >= 0 && xi < 16) acc[w] = fmaf(rin[xi], wv, acc[w]);
                }
            }
        }
    }
}

__device__ __forceinline__ void store_act(float* s_in, const float* acc, int co, int h) {
    float* row = s_in + co * 272 + h * 17;
#pragma unroll
    for (int w = 0; w < 16; w++) {
        float v = acc[w];
        row[w] = v > 0.f ? v : 0.01f * v;
    }
}

__global__ __launch_bounds__(256) void conv3_kernel(
    const float* __restrict__ x,
    const float* __restrict__ w1, const float* __restrict__ b1,
    const float* __restrict__ w2, const float* __restrict__ b2,
    const float* __restrict__ w3, const float* __restrict__ b3) {
    __shared__ float s_in[16 * 272];   // padded [ci][h(17)][w]
    __shared__ float s_w[6400];
    __shared__ float s_b[16];
    int tid = threadIdx.x;
    int img = blockIdx.x;
    const float* xi = x + (size_t)img * 4096;

    for (int i = tid; i < 4096; i += 256) {
        int c = i >> 8, r = i & 255;
        s_in[c * 272 + (r >> 4) * 17 + (r & 15)] = xi[i];
    }
    for (int i = tid; i < 6400; i += 256) s_w[i] = w1[i];
    if (tid < 16) s_b[tid] = b1[tid];
    __syncthreads();

    int co = tid >> 4, h = tid & 15;
    float acc[16];

    conv_body<5, 2>(s_in, s_w, s_b, acc, co, h);
    __syncthreads();
    store_act(s_in, acc, co, h);
    for (int i = tid; i < 2304; i += 256) s_w[i] = w2[i];
    if (tid < 16) s_b[tid] = b2[tid];
    __syncthreads();

    conv_body<3, 1>(s_in, s_w, s_b, acc, co, h);
    __syncthreads();
    store_act(s_in, acc, co, h);
    for (int i = tid; i < 2304; i += 256) s_w[i] = w3[i];
    if (tid < 16) s_b[tid] = b3[tid];
    __syncthreads();

    conv_body<3, 1>(s_in, s_w, s_b, acc, co, h);
    // final leaky + write to global (flatten c*256 + h*16 + w)
    float* og = g_conv + (size_t)img * 4096 + co * 256 + h * 16;
#pragma unroll
    for (int w = 0; w < 16; w++) {
        float v = acc[w];
        og[w] = v > 0.f ? v : 0.01f * v;
    }
}

// ----------------------------------------------------------------------------
// SGEMM: C[M,N] = act(A[M,K] * B[N,K]^T + bias (+bias2) (+z one-hot col))
// BM=BN=128, BK=8, 256 threads, 8x8 per thread.
// B row stride = ldb (>= K). ZMODE adds B[n*ldb + 512 + z[m]] (lofeat one-hot).
// ----------------------------------------------------------------------------
template <int ACT, int ZMODE>
__global__ __launch_bounds__(256, 2) void sgemm128(
    const float* __restrict__ A, const float* __restrict__ B,
    const float* __restrict__ bias, const float* __restrict__ bias2,
    float* __restrict__ C, int M, int N, int K, int ldb,
    const int* __restrict__ z) {
    __shared__ float As[8 * 132];
    __shared__ float Bs[8 * 132];
    int tid = threadIdx.x;
    int tx = tid & 15, ty = tid >> 4;
    int row0 = blockIdx.y * 128;
    int col0 = blockIdx.x * 128;
    const float* Ag = A + (size_t)row0 * K;
    const float* Bg = B + (size_t)col0 * ldb;
    int lr = tid >> 1;
    int lc = (tid & 1) * 4;

    float acc[8][8];
#pragma unroll
    for (int i = 0; i < 8; i++)
#pragma unroll
        for (int j = 0; j < 8; j++) acc[i][j] = 0.f;

    for (int k0 = 0; k0 < K; k0 += 8) {
        float4 a4 = *(const float4*)(Ag + (size_t)lr * K + k0 + lc);
        float4 b4 = *(const float4*)(Bg + (size_t)lr * ldb + k0 + lc);
        As[(lc + 0) * 132 + lr] = a4.x;
        As[(lc + 1) * 132 + lr] = a4.y;
        As[(lc + 2) * 132 + lr] = a4.z;
        As[(lc + 3) * 132 + lr] = a4.w;
        Bs[(lc + 0) * 132 + lr] = b4.x;
        Bs[(lc + 1) * 132 + lr] = b4.y;
        Bs[(lc + 2) * 132 + lr] = b4.z;
        Bs[(lc + 3) * 132 + lr] = b4.w;
        __syncthreads();
#pragma unroll
        for (int k = 0; k < 8; k++) {
            float4 a0 = *(const float4*)(As + k * 132 + ty * 4);
            float4 a1 = *(const float4*)(As + k * 132 + 64 + ty * 4);
            float4 b0 = *(const float4*)(Bs + k * 132 + tx * 4);
            float4 b1 = *(const float4*)(Bs + k * 132 + 64 + tx * 4);
            float av[8] = {a0.x, a0.y, a0.z, a0.w, a1.x, a1.y, a1.z, a1.w};
            float bv[8] = {b0.x, b0.y, b0.z, b0.w, b1.x, b1.y, b1.z, b1.w};
#pragma unroll
            for (int i = 0; i < 8; i++)
#pragma unroll
                for (int j = 0; j < 8; j++)
                    acc[i][j] = fmaf(av[i], bv[j], acc[i][j]);
        }
        __syncthreads();
    }

#pragma unroll
    for (int i = 0; i < 8; i++) {
        int m = row0 + ((i < 4) ? (ty * 4 + i) : (64 + ty * 4 + i - 4));
        int zi = 0;
        if (ZMODE) zi = 512 + z[m];
#pragma unroll
        for (int j = 0; j < 8; j++) {
            int n = col0 + ((j < 4) ? (tx * 4 + j) : (64 + tx * 4 + j - 4));
            float v = acc[i][j] + bias[n];
            if (bias2) v += bias2[n];
            if (ZMODE) v += B[(size_t)n * ldb + zi];
            if (ACT) v = v > 0.f ? v : 0.01f * v;
            C[(size_t)m * N + n] = v;
        }
    }
}

// ----------------------------------------------------------------------------
// LSTM step: gates = xg[t] + (h*m) @ w_hh^T ; fused gate nonlinearity.
// 128 blocks (4 hidden units each, all 4 gates), 128 threads.
// ----------------------------------------------------------------------------
__device__ __forceinline__ float sigm(float x) { return 1.f / (1.f + expf(-x)); }

__global__ __launch_bounds__(128) void lstm_step(
    const float* __restrict__ xg, const float* __restrict__ whh,
    const int* __restrict__ done,
    const float* __restrict__ h_in, float* __restrict__ h_out,
    float* __restrict__ c_st, float* __restrict__ feat, int t) {
    __shared__ float s_hm[128 * 36];
    __shared__ float s_w[16 * 36];
    __shared__ float s_m[128];
    int tid = threadIdx.x;
    int bn = blockIdx.x;
    int j0 = bn * 4;

    s_m[tid] = 1.0f - (float)done[t * 128 + tid];

    int jj = tid & 3;
    int b0 = (tid >> 2) * 4;

    float acc[4][4];  // [batch][gate]
#pragma unroll
    for (int bb = 0; bb < 4; bb++)
#pragma unroll
        for (int g = 0; g < 4; g++)
            acc[bb][g] = xg[(size_t)(t * 128 + b0 + bb) * 2048 + g * 512 + j0 + jj];
    __syncthreads();

    int wr = tid >> 3;           // 0..15 local weight row (g*4 + jj)
    int wc = (tid & 7) * 4;
    int wg = wr >> 2, wjj = wr & 3;
    const float* wrow = whh + (size_t)(wg * 512 + j0 + wjj) * 512;

    for (int k0 = 0; k0 < 512; k0 += 32) {
#pragma unroll
        for (int i = 0; i < 8; i++) {
            int idx = tid + 128 * i;
            int b = idx >> 3;
            int c4 = (idx & 7) * 4;
            float4 hv = *(const float4*)(h_in + b * 512 + k0 + c4);
            float mm = s_m[b];
            hv.x *= mm; hv.y *= mm; hv.z *= mm; hv.w *= mm;
            *(float4*)(s_hm + b * 36 + c4) = hv;
        }
        *(float4*)(s_w + wr * 36 + wc) = *(const float4*)(wrow + k0 + wc);
        __syncthreads();
#pragma unroll
        for (int kq = 0; kq < 8; kq++) {
            float4 wv[4];
#pragma unroll
            for (int g = 0; g < 4; g++)
                wv[g] = *(const float4*)(s_w + (g * 4 + jj) * 36 + kq * 4);
#pragma unroll
            for (int bb = 0; bb < 4; bb++) {
                float4 av = *(const float4*)(s_hm + (b0 + bb) * 36 + kq * 4);
#pragma unroll
                for (int g = 0; g < 4; g++) {
                    acc[bb][g] = fmaf(av.x, wv[g].x, acc[bb][g]);
                    acc[bb][g] = fmaf(av.y, wv[g].y, acc[bb][g]);
                    acc[bb][g] = fmaf(av.z, wv[g].z, acc[bb][g]);
                    acc[bb][g] = fmaf(av.w, wv[g].w, acc[bb][g]);
                }
            }
        }
        __syncthreads();
    }

    int j = j0 + jj;
#pragma unroll
    for (int bb = 0; bb < 4; bb++) {
        int b = b0 + bb;
        float mm = s_m[b];
        float ig = sigm(acc[bb][0]);
        float fg = sigm(acc[bb][1]);
        float gg = tanhf(acc[bb][2]);
        float og = sigm(acc[bb][3]);
        float cn = fg * (c_st[b * 512 + j] * mm) + ig * gg;
        float hn = og * tanhf(cn);
        c_st[b * 512 + j] = cn;
        h_out[b * 512 + j] = hn;
        feat[(size_t)(t * 128 + b) * 512 + j] = hn;
    }
}

// ----------------------------------------------------------------------------
// Head: warp per row; actor/critic GEMV + log_softmax/entropy/prob pack.
// out[row] = [logp[action], entropy, value, probs[7]]  (10 floats)
// ----------------------------------------------------------------------------
__global__ __launch_bounds__(256) void head_kernel(
    const float* __restrict__ lf, const float* __restrict__ aw,
    const float* __restrict__ ab, const float* __restrict__ cw,
    const float* __restrict__ cb, const int* __restrict__ action,
    float* __restrict__ out) {
    int warp = (blockIdx.x * blockDim.x + threadIdx.x) >> 5;
    int lane = threadIdx.x & 31;
    if (warp >= TBTOT) return;
    float4 f = *(const float4*)(lf + (size_t)warp * FE + lane * 4);
    float r[8];
#pragma unroll
    for (int a = 0; a < 7; a++) {
        float4 w = *(const float4*)(aw + a * FE + lane * 4);
        r[a] = f.x * w.x + f.y * w.y + f.z * w.z + f.w * w.w;
    }
    {
        float4 w = *(const float4*)(cw + lane * 4);
        r[7] = f.x * w.x + f.y * w.y + f.z * w.z + f.w * w.w;
    }
#pragma unroll
    for (int a = 0; a < 8; a++)
#pragma unroll
        for (int s = 16; s > 0; s >>= 1)
            r[a] += __shfl_xor_sync(0xffffffffu, r[a], s);

    if (lane == 0) {
        float lg[7];
        float mx = -1e30f;
#pragma unroll
        for (int a = 0; a < 7; a++) {
            lg[a] = r[a] + ab[a];
            mx = fmaxf(mx, lg[a]);
        }
        float se = 0.f;
        float e[7];
#pragma unroll
        for (int a = 0; a < 7; a++) {
            e[a] = expf(lg[a] - mx);
            se += e[a];
        }
        float lse = mx + logf(se);
        float inv = 1.f / se;
        float ent = 0.f;
        float* o = out + (size_t)warp * 10;
#pragma unroll
        for (int a = 0; a < 7; a++) {
            float p = e[a] * inv;
            float lp = lg[a] - lse;
            ent -= p * lp;
            o[3 + a] = p;
        }
        int act = action[warp];
        o[0] = lg[act] - lse;
        o[1] = ent;
        o[2] = r[7] + cb[0];
    }
}

// ----------------------------------------------------------------------------
// Launch
// ----------------------------------------------------------------------------
extern "C" void kernel_launch(void* const* d_in, const int* in_sizes, int n_in,
                              void* d_out, int out_size) {
    const float* x    = (const float*)d_in[0];
    const int* done   = (const int*)d_in[1];
    const int* z      = (const int*)d_in[2];
    const int* action = (const int*)d_in[3];
    const float* h0   = (const float*)d_in[4];
    const float* c0   = (const float*)d_in[5];
    const float* c1w = (const float*)d_in[6];  const float* c1b = (const float*)d_in[7];
    const float* c2w = (const float*)d_in[8];  const float* c2b = (const float*)d_in[9];
    const float* c3w = (const float*)d_in[10]; const float* c3b = (const float*)d_in[11];
    const float* fc1w = (const float*)d_in[12]; const float* fc1b = (const float*)d_in[13];
    const float* fc2w = (const float*)d_in[14]; const float* fc2b = (const float*)d_in[15];
    const float* wih = (const float*)d_in[16]; const float* whh = (const float*)d_in[17];
    const float* bih = (const float*)d_in[18]; const float* bhh = (const float*)d_in[19];
    const float* lfw = (const float*)d_in[20]; const float* lfb = (const float*)d_in[21];
    const float* aw = (const float*)d_in[22];  const float* ab = (const float*)d_in[23];
    const float* cw = (const float*)d_in[24];  const float* cb = (const float*)d_in[25];
    float* out = (float*)d_out;

    float *pconv, *ph1, *ph2, *pxg, *pfeat, *plf, *phA, *phB, *pc;
    cudaGetSymbolAddress((void**)&pconv, g_conv);
    cudaGetSymbolAddress((void**)&ph1, g_h1);
    cudaGetSymbolAddress((void**)&ph2, g_h2);
    cudaGetSymbolAddress((void**)&pxg, g_xg);
    cudaGetSymbolAddress((void**)&pfeat, g_feat);
    cudaGetSymbolAddress((void**)&plf, g_lf);
    cudaGetSymbolAddress((void**)&phA, g_hA);
    cudaGetSymbolAddress((void**)&phB, g_hB);
    cudaGetSymbolAddress((void**)&pc, g_c);

    // conv stack
    conv3_kernel<<<TBTOT, 256>>>(x, c1w, c1b, c2w, c2b, c3w, c3b);

    // fc1: [16384,4096] x [512,4096]^T -> leaky
    sgemm128<1, 0><<<dim3(512 / 128, TBTOT / 128), 256>>>(
        pconv, fc1w, fc1b, nullptr, ph1, TBTOT, 512, 4096, 4096, nullptr);
    // fc2
    sgemm128<1, 0><<<dim3(512 / 128, TBTOT / 128), 256>>>(
        ph1, fc2w, fc2b, nullptr, ph2, TBTOT, 512, 512, 512, nullptr);
    // input gates (both biases folded), no activation
    sgemm128<0, 0><<<dim3(2048 / 128, TBTOT / 128), 256>>>(
        ph2, wih, bih, bhh, pxg, TBTOT, 2048, 512, 512, nullptr);

    // initial LSTM state
    cudaMemcpyAsync(phA, h0, (size_t)B_ENV * HID * sizeof(float),
                    cudaMemcpyDeviceToDevice, 0);
    cudaMemcpyAsync(pc, c0, (size_t)B_ENV * HID * sizeof(float),
                    cudaMemcpyDeviceToDevice, 0);

    // sequential recurrence, ping-pong h
    for (int t = 0; t < T_STEPS; t++) {
        float* hin = (t & 1) ? phB : phA;
        float* hout = (t & 1) ? phA : phB;
        lstm_step<<<128, 128>>>(pxg, whh, done, hin, hout, pc, pfeat, t);
    }

    // lofeat: feat(512) + one-hot(z) via epilogue, ldb=520, leaky
    sgemm128<1, 1><<<dim3(FE / 128, TBTOT / 128), 256>>>(
        pfeat, lfw, lfb, nullptr, plf, TBTOT, FE, 512, 520, z);

    // heads + softmax stats
    head_kernel<<<TBTOT / 8, 256>>>(plf, aw, ab, cw, cb, action, out);
}

// round 3
// speedup vs baseline: 1.3306x; 1.3306x over previous
#include <cuda_runtime.h>
#include <cuda_bf16.h>
#include <math.h>
#include <stdint.h>

#define T_STEPS 128
#define B_ENV   128
#define HID     512
#define TBTOT   (T_STEPS * B_ENV)
#define ZD      8
#define AD      7
#define FE      128

// ----------------------------------------------------------------------------
// Scratch (device globals; no allocation allowed)
// ----------------------------------------------------------------------------
__device__ float g_conv[TBTOT * 4096];   // conv output / fc1 input
__device__ float g_h1[TBTOT * HID];
__device__ float g_h2[TBTOT * HID];
__device__ float g_xg[TBTOT * 2048];     // precomputed input gates
__device__ float g_feat[TBTOT * HID];
__device__ float g_lf[TBTOT * FE];
__device__ float g_hA[B_ENV * HID];
__device__ float g_hB[B_ENV * HID];
__device__ float g_c[B_ENV * HID];
// pre-split bf16 weights (row-major [N][K], hi and lo parts)
__device__ __nv_bfloat16 g_wfc1_hi[512 * 4096];
__device__ __nv_bfloat16 g_wfc1_lo[512 * 4096];
__device__ __nv_bfloat16 g_wfc2_hi[512 * 512];
__device__ __nv_bfloat16 g_wfc2_lo[512 * 512];
__device__ __nv_bfloat16 g_wih_hi[2048 * 512];
__device__ __nv_bfloat16 g_wih_lo[2048 * 512];

// ============================================================================
// Helpers
// ============================================================================
__device__ __forceinline__ uint32_t smem_to_u32(const void* smem_ptr) {
    uint32_t addr;
    asm("{ .reg .u64 tmp; cvta.to.shared.u64 tmp, %1; cvt.u32.u64 %0, tmp; }"
        : "=r"(addr) : "l"(smem_ptr));
    return addr;
}

__device__ __forceinline__ void ldsm4(uint32_t addr, uint32_t* r) {
    asm volatile("ldmatrix.sync.aligned.m8n8.x4.shared.b16 {%0,%1,%2,%3}, [%4];"
        : "=r"(r[0]), "=r"(r[1]), "=r"(r[2]), "=r"(r[3]) : "r"(addr));
}

__device__ __forceinline__ void mma16816(float* d, const uint32_t* a,
                                         const uint32_t* b) {
    asm volatile(
        "mma.sync.aligned.m16n8k16.row.col.f32.bf16.bf16.f32 "
        "{%0,%1,%2,%3}, {%4,%5,%6,%7}, {%8,%9}, {%0,%1,%2,%3};"
        : "+f"(d[0]), "+f"(d[1]), "+f"(d[2]), "+f"(d[3])
        : "r"(a[0]), "r"(a[1]), "r"(a[2]), "r"(a[3]), "r"(b[0]), "r"(b[1]));
}

// split fp32 pair -> packed bf16x2 hi + bf16x2 lo
__device__ __forceinline__ void split2(float x, float y, uint32_t& hi, uint32_t& lo) {
    __nv_bfloat16 hx = __float2bfloat16(x), hy = __float2bfloat16(y);
    __nv_bfloat162 h2; h2.x = hx; h2.y = hy;
    hi = reinterpret_cast<uint32_t&>(h2);
    float lx = x - __bfloat162float(hx);
    float ly = y - __bfloat162float(hy);
    __nv_bfloat162 l2 = __floats2bfloat162_rn(lx, ly);
    lo = reinterpret_cast<uint32_t&>(l2);
}

// ----------------------------------------------------------------------------
// Weight prep: fp32 [N,K] row-major -> bf16 hi/lo row-major
// ----------------------------------------------------------------------------
__global__ void wprep(const float* __restrict__ w, __nv_bfloat16* __restrict__ hi,
                      __nv_bfloat16* __restrict__ lo, int total4) {
    int idx = blockIdx.x * blockDim.x + threadIdx.x;
    if (idx >= total4) return;
    float4 a = *(const float4*)(w + (size_t)idx * 4);
    uint32_t h0, h1, l0, l1;
    split2(a.x, a.y, h0, l0);
    split2(a.z, a.w, h1, l1);
    *(uint2*)(hi + (size_t)idx * 4) = make_uint2(h0, h1);
    *(uint2*)(lo + (size_t)idx * 4) = make_uint2(l0, l1);
}

// ----------------------------------------------------------------------------
// HMMA GEMM: C[M,N] = act(A[M,K]fp32 * W[N,K]^T + bias (+bias2))
// 3-term bf16 split (AhBh + AhBl + AlBh), fp32 accum.
// 128x128 block, BK=32, 8 warps (warp tile 32x64), smem rows padded to 80B.
// ----------------------------------------------------------------------------
#define SMSTR 80   // bytes per smem row (32 bf16 data + 8 pad)

template <int ACT>
__global__ __launch_bounds__(256) void tgemm(
    const float* __restrict__ A, const __nv_bfloat16* __restrict__ Whi,
    const __nv_bfloat16* __restrict__ Wlo,
    const float* __restrict__ bias, const float* __restrict__ bias2,
    float* __restrict__ C, int M, int N, int K) {
    extern __shared__ uint8_t sm[];
    const uint32_t oAh = 0, oAl = 10240, oBh = 20480, oBl = 30720;
    uint32_t sb = smem_to_u32(sm);
    int tid = threadIdx.x;
    int lane = tid & 31;
    int wid = tid >> 5;
    int wm = wid & 3, wn = wid >> 2;
    int m0 = blockIdx.y * 128, n0 = blockIdx.x * 128;
    const float* Ag = A + (size_t)m0 * K;

    float acc[2][8][4];
#pragma unroll
    for (int i = 0; i < 2; i++)
#pragma unroll
        for (int j = 0; j < 8; j++)
#pragma unroll
            for (int q = 0; q < 4; q++) acc[i][j][q] = 0.f;

    int nslab = K / 32;
    float4 aR[4];
    uint4 bRh[2], bRl[2];

    // slab load (gmem -> regs)
    auto load_slab = [&](int s) {
#pragma unroll
        for (int i = 0; i < 4; i++) {
            int row = (tid >> 3) + 32 * i;
            aR[i] = *(const float4*)(Ag + (size_t)row * K + s * 32 + (tid & 7) * 4);
        }
#pragma unroll
        for (int i = 0; i < 2; i++) {
            int row = (tid >> 2) + 64 * i;
            size_t boff = ((size_t)(n0 + row) * K + s * 32);
            bRh[i] = *(const uint4*)((const uint8_t*)(Whi + boff) + (tid & 3) * 16);
            bRl[i] = *(const uint4*)((const uint8_t*)(Wlo + boff) + (tid & 3) * 16);
        }
    };
    // slab store (regs -> smem, A split to hi/lo)
    auto store_slab = [&]() {
#pragma unroll
        for (int i = 0; i < 4; i++) {
            int row = (tid >> 3) + 32 * i;
            int col8 = (tid & 7) * 8;
            uint32_t h0, h1, l0, l1;
            split2(aR[i].x, aR[i].y, h0, l0);
            split2(aR[i].z, aR[i].w, h1, l1);
            *(uint2*)(sm + oAh + row * SMSTR + col8) = make_uint2(h0, h1);
            *(uint2*)(sm + oAl + row * SMSTR + col8) = make_uint2(l0, l1);
        }
#pragma unroll
        for (int i = 0; i < 2; i++) {
            int row = (tid >> 2) + 64 * i;
            int c16 = (tid & 3) * 16;
            *(uint4*)(sm + oBh + row * SMSTR + c16) = bRh[i];
            *(uint4*)(sm + oBl + row * SMSTR + c16) = bRl[i];
        }
    };

    load_slab(0);
    store_slab();
    __syncthreads();

    int g = lane >> 3;
    int arow_off = (lane & 7) + (g & 1) * 8;
    int akb_off = (g >> 1) * 16;
    int brow_off = (lane & 7) + (g >> 1) * 8;
    int bkb_off = (g & 1) * 16;

    for (int s = 0; s < nslab; s++) {
        bool more = (s + 1 < nslab);
        if (more) load_slab(s + 1);

#pragma unroll
        for (int kk2 = 0; kk2 < 2; kk2++) {
            int kb = kk2 * 32;
            uint32_t ah[2][4], al[2][4], bh[4][4], bl[4][4];
#pragma unroll
            for (int mi = 0; mi < 2; mi++) {
                uint32_t r = (uint32_t)((wm * 32 + mi * 16 + arow_off) * SMSTR +
                                        kb + akb_off);
                ldsm4(sb + oAh + r, ah[mi]);
                ldsm4(sb + oAl + r, al[mi]);
            }
#pragma unroll
            for (int pi = 0; pi < 4; pi++) {
                uint32_t r = (uint32_t)((wn * 64 + pi * 16 + brow_off) * SMSTR +
                                        kb + bkb_off);
                ldsm4(sb + oBh + r, bh[pi]);
                ldsm4(sb + oBl + r, bl[pi]);
            }
#pragma unroll
            for (int mi = 0; mi < 2; mi++)
#pragma unroll
                for (int pi = 0; pi < 4; pi++)
#pragma unroll
                    for (int half = 0; half < 2; half++) {
                        float* d = acc[mi][pi * 2 + half];
                        mma16816(d, ah[mi], &bh[pi][half * 2]);
                        mma16816(d, ah[mi], &bl[pi][half * 2]);
                        mma16816(d, al[mi], &bh[pi][half * 2]);
                    }
        }
        __syncthreads();
        if (more) {
            store_slab();
            __syncthreads();
        }
    }

    // epilogue: frags -> smem (bias+act applied) -> coalesced gmem
    float* ct = (float*)sm;  // 128 x 132
#pragma unroll
    for (int mi = 0; mi < 2; mi++) {
        int r0 = wm * 32 + mi * 16 + (lane >> 2);
#pragma unroll
        for (int ni = 0; ni < 8; ni++) {
            int c = wn * 64 + ni * 8 + (lane & 3) * 2;
            float b0 = bias[n0 + c], b1 = bias[n0 + c + 1];
            if (bias2) { b0 += bias2[n0 + c]; b1 += bias2[n0 + c + 1]; }
            float v0 = acc[mi][ni][0] + b0;
            float v1 = acc[mi][ni][1] + b1;
            float v2 = acc[mi][ni][2] + b0;
            float v3 = acc[mi][ni][3] + b1;
            if (ACT) {
                v0 = v0 > 0.f ? v0 : 0.01f * v0;
                v1 = v1 > 0.f ? v1 : 0.01f * v1;
                v2 = v2 > 0.f ? v2 : 0.01f * v2;
                v3 = v3 > 0.f ? v3 : 0.01f * v3;
            }
            ct[r0 * 132 + c] = v0;
            ct[r0 * 132 + c + 1] = v1;
            ct[(r0 + 8) * 132 + c] = v2;
            ct[(r0 + 8) * 132 + c + 1] = v3;
        }
    }
    __syncthreads();
    {
        int r8 = tid >> 5;
        int c4 = (tid & 31) * 4;
#pragma unroll
        for (int p = 0; p < 16; p++) {
            int r = p * 8 + r8;
            float4 v = *(const float4*)(ct + r * 132 + c4);
            *(float4*)(C + (size_t)(m0 + r) * N + n0 + c4) = v;
        }
    }
}

// ----------------------------------------------------------------------------
// Fused 3-conv kernel (unchanged)
// ----------------------------------------------------------------------------
template <int KS, int P>
__device__ __forceinline__ void conv_body(const float* __restrict__ s_in,
                                          const float* __restrict__ s_w,
                                          const float* __restrict__ s_b,
                                          float* acc, int co, int h) {
    float bv = s_b[co];
#pragma unroll
    for (int w = 0; w < 16; w++) acc[w] = bv;
    for (int ci = 0; ci < 16; ci++) {
        const float* wbase = s_w + (co * 16 + ci) * KS * KS;
#pragma unroll
        for (int kh = 0; kh < KS; kh++) {
            int hy = h + kh - P;
            if (hy < 0 || hy > 15) continue;
            const float* row = s_in + ci * 272 + hy * 17;
            float rin[16];
#pragma unroll
            for (int w = 0; w < 16; w++) rin[w] = row[w];
#pragma unroll
            for (int kw = 0; kw < KS; kw++) {
                float wv = wbase[kh * KS + kw];
#pragma unroll
                for (int w = 0; w < 16; w++) {
                    int xi = w + kw - P;
                    if (xi >= 0 && xi < 16) acc[w] = fmaf(rin[xi], wv, acc[w]);
                }
            }
        }
    }
}

__device__ __forceinline__ void store_act(float* s_in, const float* acc, int co, int h) {
    float* row = s_in + co * 272 + h * 17;
#pragma unroll
    for (int w = 0; w < 16; w++) {
        float v = acc[w];
        row[w] = v > 0.f ? v : 0.01f * v;
    }
}

__global__ __launch_bounds__(256) void conv3_kernel(
    const float* __restrict__ x,
    const float* __restrict__ w1, const float* __restrict__ b1,
    const float* __restrict__ w2, const float* __restrict__ b2,
    const float* __restrict__ w3, const float* __restrict__ b3) {
    __shared__ float s_in[16 * 272];
    __shared__ float s_w[6400];
    __shared__ float s_b[16];
    int tid = threadIdx.x;
    int img = blockIdx.x;
    const float* xi = x + (size_t)img * 4096;

    for (int i = tid; i < 4096; i += 256) {
        int c = i >> 8, r = i & 255;
        s_in[c * 272 + (r >> 4) * 17 + (r & 15)] = xi[i];
    }
    for (int i = tid; i < 6400; i += 256) s_w[i] = w1[i];
    if (tid < 16) s_b[tid] = b1[tid];
    __syncthreads();

    int co = tid >> 4, h = tid & 15;
    float acc[16];

    conv_body<5, 2>(s_in, s_w, s_b, acc, co, h);
    __syncthreads();
    store_act(s_in, acc, co, h);
    for (int i = tid; i < 2304; i += 256) s_w[i] = w2[i];
    if (tid < 16) s_b[tid] = b2[tid];
    __syncthreads();

    conv_body<3, 1>(s_in, s_w, s_b, acc, co, h);
    __syncthreads();
    store_act(s_in, acc, co, h);
    for (int i = tid; i < 2304; i += 256) s_w[i] = w3[i];
    if (tid < 16) s_b[tid] = b3[tid];
    __syncthreads();

    conv_body<3, 1>(s_in, s_w, s_b, acc, co, h);
    float* og = g_conv + (size_t)img * 4096 + co * 256 + h * 16;
#pragma unroll
    for (int w = 0; w < 16; w++) {
        float v = acc[w];
        og[w] = v > 0.f ? v : 0.01f * v;
    }
}

// ----------------------------------------------------------------------------
// Scalar SGEMM kept for lofeat (with z one-hot epilogue)
// ----------------------------------------------------------------------------
template <int ACT, int ZMODE>
__global__ __launch_bounds__(256, 2) void sgemm128(
    const float* __restrict__ A, const float* __restrict__ B,
    const float* __restrict__ bias, const float* __restrict__ bias2,
    float* __restrict__ C, int M, int N, int K, int ldb,
    const int* __restrict__ z) {
    __shared__ float As[8 * 132];
    __shared__ float Bs[8 * 132];
    int tid = threadIdx.x;
    int tx = tid & 15, ty = tid >> 4;
    int row0 = blockIdx.y * 128;
    int col0 = blockIdx.x * 128;
    const float* Ag = A + (size_t)row0 * K;
    const float* Bg = B + (size_t)col0 * ldb;
    int lr = tid >> 1;
    int lc = (tid & 1) * 4;

    float acc[8][8];
#pragma unroll
    for (int i = 0; i < 8; i++)
#pragma unroll
        for (int j = 0; j < 8; j++) acc[i][j] = 0.f;

    for (int k0 = 0; k0 < K; k0 += 8) {
        float4 a4 = *(const float4*)(Ag + (size_t)lr * K + k0 + lc);
        float4 b4 = *(const float4*)(Bg + (size_t)lr * ldb + k0 + lc);
        As[(lc + 0) * 132 + lr] = a4.x;
        As[(lc + 1) * 132 + lr] = a4.y;
        As[(lc + 2) * 132 + lr] = a4.z;
        As[(lc + 3) * 132 + lr] = a4.w;
        Bs[(lc + 0) * 132 + lr] = b4.x;
        Bs[(lc + 1) * 132 + lr] = b4.y;
        Bs[(lc + 2) * 132 + lr] = b4.z;
        Bs[(lc + 3) * 132 + lr] = b4.w;
        __syncthreads();
#pragma unroll
        for (int k = 0; k < 8; k++) {
            float4 a0 = *(const float4*)(As + k * 132 + ty * 4);
            float4 a1 = *(const float4*)(As + k * 132 + 64 + ty * 4);
            float4 b0 = *(const float4*)(Bs + k * 132 + tx * 4);
            float4 b1 = *(const float4*)(Bs + k * 132 + 64 + tx * 4);
            float av[8] = {a0.x, a0.y, a0.z, a0.w, a1.x, a1.y, a1.z, a1.w};
            float bv[8] = {b0.x, b0.y, b0.z, b0.w, b1.x, b1.y, b1.z, b1.w};
#pragma unroll
            for (int i = 0; i < 8; i++)
#pragma unroll
                for (int j = 0; j < 8; j++)
                    acc[i][j] = fmaf(av[i], bv[j], acc[i][j]);
        }
        __syncthreads();
    }

#pragma unroll
    for (int i = 0; i < 8; i++) {
        int m = row0 + ((i < 4) ? (ty * 4 + i) : (64 + ty * 4 + i - 4));
        int zi = 0;
        if (ZMODE) zi = 512 + z[m];
#pragma unroll
        for (int j = 0; j < 8; j++) {
            int n = col0 + ((j < 4) ? (tx * 4 + j) : (64 + tx * 4 + j - 4));
            float v = acc[i][j] + bias[n];
            if (bias2) v += bias2[n];
            if (ZMODE) v += B[(size_t)n * ldb + zi];
            if (ACT) v = v > 0.f ? v : 0.01f * v;
            C[(size_t)m * N + n] = v;
        }
    }
}

// ----------------------------------------------------------------------------
// LSTM step (256 threads: 2 batches x 4 gates per thread, 4 j per block)
// ----------------------------------------------------------------------------
__device__ __forceinline__ float sigm(float x) { return 1.f / (1.f + expf(-x)); }

__global__ __launch_bounds__(256) void lstm_step(
    const float* __restrict__ xg, const float* __restrict__ whh,
    const int* __restrict__ done,
    const float* __restrict__ h_in, float* __restrict__ h_out,
    float* __restrict__ c_st, float* __restrict__ feat, int t) {
    __shared__ float s_hm[128 * 36];
    __shared__ float s_w[16 * 36];
    __shared__ float s_m[128];
    int tid = threadIdx.x;
    int bn = blockIdx.x;
    int j0 = bn * 4;

    if (tid < 128) s_m[tid] = 1.0f - (float)done[t * 128 + tid];

    int jj = tid & 3;
    int b0 = (tid >> 2) * 2;

    float acc[2][4];
#pragma unroll
    for (int bb = 0; bb < 2; bb++)
#pragma unroll
        for (int g = 0; g < 4; g++)
            acc[bb][g] = xg[(size_t)(t * 128 + b0 + bb) * 2048 + g * 512 + j0 + jj];
    __syncthreads();

    int wr = tid >> 3;
    int wc = (tid & 7) * 4;
    int wg = wr >> 2, wjj = wr & 3;
    const float* wrow = whh + (size_t)(wg * 512 + j0 + wjj) * 512;

    for (int k0 = 0; k0 < 512; k0 += 32) {
#pragma unroll
        for (int i = 0; i < 4; i++) {
            int idx = tid + 256 * i;
            int b = idx >> 3;
            int c4 = (idx & 7) * 4;
            float4 hv = *(const float4*)(h_in + b * 512 + k0 + c4);
            float mm = s_m[b];
            hv.x *= mm; hv.y *= mm; hv.z *= mm; hv.w *= mm;
            *(float4*)(s_hm + b * 36 + c4) = hv;
        }
        if (tid < 128)
            *(float4*)(s_w + wr * 36 + wc) = *(const float4*)(wrow + k0 + wc);
        __syncthreads();
#pragma unroll
        for (int kq = 0; kq < 8; kq++) {
            float4 wv[4];
#pragma unroll
            for (int g = 0; g < 4; g++)
                wv[g] = *(const float4*)(s_w + (g * 4 + jj) * 36 + kq * 4);
#pragma unroll
            for (int bb = 0; bb < 2; bb++) {
                float4 av = *(const float4*)(s_hm + (b0 + bb) * 36 + kq * 4);
#pragma unroll
                for (int g = 0; g < 4; g++) {
                    acc[bb][g] = fmaf(av.x, wv[g].x, acc[bb][g]);
                    acc[bb][g] = fmaf(av.y, wv[g].y, acc[bb][g]);
                    acc[bb][g] = fmaf(av.z, wv[g].z, acc[bb][g]);
                    acc[bb][g] = fmaf(av.w, wv[g].w, acc[bb][g]);
                }
            }
        }
        __syncthreads();
    }

    int j = j0 + jj;
#pragma unroll
    for (int bb = 0; bb < 2; bb++) {
        int b = b0 + bb;
        float mm = s_m[b];
        float ig = sigm(acc[bb][0]);
        float fg = sigm(acc[bb][1]);
        float gg = tanhf(acc[bb][2]);
        float og = sigm(acc[bb][3]);
        float cn = fg * (c_st[b * 512 + j] * mm) + ig * gg;
        float hn = og * tanhf(cn);
        c_st[b * 512 + j] = cn;
        h_out[b * 512 + j] = hn;
        feat[(size_t)(t * 128 + b) * 512 + j] = hn;
    }
}

// ----------------------------------------------------------------------------
// Head: warp per row; actor/critic GEMV + log_softmax/entropy/prob pack.
// ----------------------------------------------------------------------------
__global__ __launch_bounds__(256) void head_kernel(
    const float* __restrict__ lf, const float* __restrict__ aw,
    const float* __restrict__ ab, const float* __restrict__ cw,
    const float* __restrict__ cb, const int* __restrict__ action,
    float* __restrict__ out) {
    int warp = (blockIdx.x * blockDim.x + threadIdx.x) >> 5;
    int lane = threadIdx.x & 31;
    if (warp >= TBTOT) return;
    float4 f = *(const float4*)(lf + (size_t)warp * FE + lane * 4);
    float r[8];
#pragma unroll
    for (int a = 0; a < 7; a++) {
        float4 w = *(const float4*)(aw + a * FE + lane * 4);
        r[a] = f.x * w.x + f.y * w.y + f.z * w.z + f.w * w.w;
    }
    {
        float4 w = *(const float4*)(cw + lane * 4);
        r[7] = f.x * w.x + f.y * w.y + f.z * w.z + f.w * w.w;
    }
#pragma unroll
    for (int a = 0; a < 8; a++)
#pragma unroll
        for (int s = 16; s > 0; s >>= 1)
            r[a] += __shfl_xor_sync(0xffffffffu, r[a], s);

    if (lane == 0) {
        float lg[7];
        float mx = -1e30f;
#pragma unroll
        for (int a = 0; a < 7; a++) {
            lg[a] = r[a] + ab[a];
            mx = fmaxf(mx, lg[a]);
        }
        float se = 0.f;
        float e[7];
#pragma unroll
        for (int a = 0; a < 7; a++) {
            e[a] = expf(lg[a] - mx);
            se += e[a];
        }
        float lse = mx + logf(se);
        float inv = 1.f / se;
        float ent = 0.f;
        float* o = out + (size_t)warp * 10;
#pragma unroll
        for (int a = 0; a < 7; a++) {
            float p = e[a] * inv;
            float lp = lg[a] - lse;
            ent -= p * lp;
            o[3 + a] = p;
        }
        int act = action[warp];
        o[0] = lg[act] - lse;
        o[1] = ent;
        o[2] = r[7] + cb[0];
    }
}

// ----------------------------------------------------------------------------
// Launch
// ----------------------------------------------------------------------------
extern "C" void kernel_launch(void* const* d_in, const int* in_sizes, int n_in,
                              void* d_out, int out_size) {
    const float* x    = (const float*)d_in[0];
    const int* done   = (const int*)d_in[1];
    const int* z      = (const int*)d_in[2];
    const int* action = (const int*)d_in[3];
    const float* h0   = (const float*)d_in[4];
    const float* c0   = (const float*)d_in[5];
    const float* c1w = (const float*)d_in[6];  const float* c1b = (const float*)d_in[7];
    const float* c2w = (const float*)d_in[8];  const float* c2b = (const float*)d_in[9];
    const float* c3w = (const float*)d_in[10]; const float* c3b = (const float*)d_in[11];
    const float* fc1w = (const float*)d_in[12]; const float* fc1b = (const float*)d_in[13];
    const float* fc2w = (const float*)d_in[14]; const float* fc2b = (const float*)d_in[15];
    const float* wih = (const float*)d_in[16]; const float* whh = (const float*)d_in[17];
    const float* bih = (const float*)d_in[18]; const float* bhh = (const float*)d_in[19];
    const float* lfw = (const float*)d_in[20]; const float* lfb = (const float*)d_in[21];
    const float* aw = (const float*)d_in[22];  const float* ab = (const float*)d_in[23];
    const float* cw = (const float*)d_in[24];  const float* cb = (const float*)d_in[25];
    float* out = (float*)d_out;

    float *pconv, *ph1, *ph2, *pxg, *pfeat, *plf, *phA, *phB, *pc;
    __nv_bfloat16 *pw1h, *pw1l, *pw2h, *pw2l, *pwih_h, *pwih_l;
    cudaGetSymbolAddress((void**)&pconv, g_conv);
    cudaGetSymbolAddress((void**)&ph1, g_h1);
    cudaGetSymbolAddress((void**)&ph2, g_h2);
    cudaGetSymbolAddress((void**)&pxg, g_xg);
    cudaGetSymbolAddress((void**)&pfeat, g_feat);
    cudaGetSymbolAddress((void**)&plf, g_lf);
    cudaGetSymbolAddress((void**)&phA, g_hA);
    cudaGetSymbolAddress((void**)&phB, g_hB);
    cudaGetSymbolAddress((void**)&pc, g_c);
    cudaGetSymbolAddress((void**)&pw1h, g_wfc1_hi);
    cudaGetSymbolAddress((void**)&pw1l, g_wfc1_lo);
    cudaGetSymbolAddress((void**)&pw2h, g_wfc2_hi);
    cudaGetSymbolAddress((void**)&pw2l, g_wfc2_lo);
    cudaGetSymbolAddress((void**)&pwih_h, g_wih_hi);
    cudaGetSymbolAddress((void**)&pwih_l, g_wih_lo);

    const int SMEM_TG = 128 * 132 * 4;  // 67584 (epilogue superset of pipeline)
    cudaFuncSetAttribute(tgemm<1>, cudaFuncAttributeMaxDynamicSharedMemorySize, SMEM_TG);
    cudaFuncSetAttribute(tgemm<0>, cudaFuncAttributeMaxDynamicSharedMemorySize, SMEM_TG);

    // weight prep (split fp32 -> bf16 hi/lo)
    wprep<<<(512 * 1024 + 255) / 256, 256>>>(fc1w, pw1h, pw1l, 512 * 1024);
    wprep<<<(512 * 128 + 255) / 256, 256>>>(fc2w, pw2h, pw2l, 512 * 128);
    wprep<<<(2048 * 128 + 255) / 256, 256>>>(wih, pwih_h, pwih_l, 2048 * 128);

    // conv stack
    conv3_kernel<<<TBTOT, 256>>>(x, c1w, c1b, c2w, c2b, c3w, c3b);

    // tensor-core (HMMA) GEMMs
    tgemm<1><<<dim3(512 / 128, TBTOT / 128), 256, SMEM_TG>>>(
        pconv, pw1h, pw1l, fc1b, nullptr, ph1, TBTOT, 512, 4096);
    tgemm<1><<<dim3(512 / 128, TBTOT / 128), 256, SMEM_TG>>>(
        ph1, pw2h, pw2l, fc2b, nullptr, ph2, TBTOT, 512, 512);
    tgemm<0><<<dim3(2048 / 128, TBTOT / 128), 256, SMEM_TG>>>(
        ph2, pwih_h, pwih_l, bih, bhh, pxg, TBTOT, 2048, 512);

    // initial LSTM state
    cudaMemcpyAsync(phA, h0, (size_t)B_ENV * HID * sizeof(float),
                    cudaMemcpyDeviceToDevice, 0);
    cudaMemcpyAsync(pc, c0, (size_t)B_ENV * HID * sizeof(float),
                    cudaMemcpyDeviceToDevice, 0);

    // sequential recurrence, ping-pong h
    for (int t = 0; t < T_STEPS; t++) {
        float* hin = (t & 1) ? phB : phA;
        float* hout = (t & 1) ? phA : phB;
        lstm_step<<<128, 256>>>(pxg, whh, done, hin, hout, pc, pfeat, t);
    }

    // lofeat: feat(512) + one-hot(z) via epilogue, ldb=520, leaky
    sgemm128<1, 1><<<dim3(FE / 128, TBTOT / 128), 256>>>(
        pfeat, lfw, lfb, nullptr, plf, TBTOT, FE, 512, 520, z);

    // heads + softmax stats
    head_kernel<<<TBTOT / 8, 256>>>(plf, aw, ab, cw, cb, action, out);
}